// round 10
// baseline (speedup 1.0000x reference)
#include <cuda_runtime.h>
#include <cuda_bf16.h>
#include <math.h>
#include <stdint.h>

// Problem constants
#define B_    64
#define PANO_ 36
#define OBJ_  36
#define CFG_  16
#define LM_   8
#define IMG_  32
#define D_    300
#define H_    512
#define EMB_  64
#define ANG_  128
#define FEAT_ 2176
#define TOPN_ 3
#define M_    128
#define EPS_  1e-8f

// Output layout (flattened tuple): h_1 | c_1 | logit | h_tilde | ctx_attn
#define OFF_H1   0
#define OFF_C1   32768
#define OFF_LOG  65536
#define OFF_HT   67584
#define OFF_CA   100352

// ---------------- scratch ----------------
__device__ __align__(256) float g_x[B_*3140];      // [action_emb(64) | attn_feat(3076)]
__device__ __align__(256) float g_qfeat[B_*3076];
__device__ __align__(256) float g_cat[B_*1024];
__device__ __align__(256) float g_q2[B_*3097];
__device__ __align__(256) float g_gates[B_*2048];
__device__ __align__(256) float g_qa[B_*H_];
__device__ __align__(256) float g_part[4*64*2048]; // split-K partials
__device__ float g_pano_sim[B_*PANO_*900];
__device__ float g_a[B_*PANO_];
__device__ int   g_top1[B_*3];
__device__ float g_nb1[B_*3];
__device__ int   g_top2[B_*3];
__device__ float g_nb2[B_*3];
__device__ float g_relmask[B_*3];
__device__ float g_landrel[B_*18];

// ---------------- helpers ----------------
__device__ __forceinline__ float wred(float v) {
    #pragma unroll
    for (int o = 16; o; o >>= 1) v += __shfl_down_sync(0xffffffffu, v, o);
    return v;
}
__device__ __forceinline__ float block_reduce(float v, float* sbuf) {
    int lane = threadIdx.x & 31, w = threadIdx.x >> 5;
    v = wred(v);
    if (lane == 0) sbuf[w] = v;
    __syncthreads();
    int nw = blockDim.x >> 5;
    v = (threadIdx.x < nw) ? sbuf[threadIdx.x] : 0.f;
    if (w == 0) v = wred(v);
    return v;
}
__device__ __forceinline__ float sigmoidf_(float x) { return 1.f / (1.f + expf(-x)); }
__device__ __forceinline__ uint32_t to_tf32(float x) {
    uint32_t r; asm("cvt.rna.tf32.f32 %0, %1;" : "=r"(r) : "f"(x)); return r;
}
// TF32x3 split: x ~= hi + lo, both exactly representable in tf32
__device__ __forceinline__ void split_tf32(float x, uint32_t& hi, uint32_t& lo) {
    hi = to_tf32(x);
    lo = to_tf32(x - __uint_as_float(hi));
}
__device__ __forceinline__ void mma_tf32(float* acc, const uint32_t* a, const uint32_t* b) {
    asm volatile(
        "mma.sync.aligned.m16n8k8.row.col.f32.tf32.tf32.f32 "
        "{%0,%1,%2,%3}, {%4,%5,%6,%7}, {%8,%9}, {%0,%1,%2,%3};"
        : "+f"(acc[0]), "+f"(acc[1]), "+f"(acc[2]), "+f"(acc[3])
        : "r"(a[0]), "r"(a[1]), "r"(a[2]), "r"(a[3]), "r"(b[0]), "r"(b[1]));
}

// ---------------- action embedding ----------------
__global__ void k_action_embed(const float* __restrict__ action,
                               const float* __restrict__ embW,
                               const float* __restrict__ embB) {
    int idx = blockIdx.x * 128 + threadIdx.x;
    if (idx >= B_ * EMB_) return;
    int b = idx >> 6, e = idx & 63;
    float acc = embB[e];
    const float* a = action + b * ANG_;
    #pragma unroll 4
    for (int k = 0; k < ANG_; k++) acc += a[k] * embW[k * EMB_ + e];
    g_x[(size_t)b * 3140 + e] = tanhf(acc);
}

// ---------------- TF32x3 tensor-core GEMM: C[64,N] = A[64,K] @ W[K,N] ----------------
// mode 0: direct write (+bias); mode 1: split-K partial to out + blockIdx.y*64*N;
// mode 2: direct write with tanh epilogue (+bias)
__global__ void __launch_bounds__(256) k_gemm_tc(
        const float* __restrict__ A, int lda,
        const float* __restrict__ W, int N, int K, int kChunk,
        float* __restrict__ out, const float* __restrict__ bias, int mode) {
    int n0 = blockIdx.x * 64;
    int k0 = blockIdx.y * kChunk;
    int kEnd = min(K, k0 + kChunk);
    __shared__ float sA[64][36];
    __shared__ float sW[32][72];
    int tid  = threadIdx.x;
    int warp = tid >> 5, lane = tid & 31;
    int wm = warp >> 2, wn = warp & 3;        // 2 x 4 warp grid
    int g  = lane >> 2, tg = lane & 3;        // groupID, thread-in-group

    float acc[2][2][4];
    #pragma unroll
    for (int mt = 0; mt < 2; mt++)
        #pragma unroll
        for (int nt = 0; nt < 2; nt++)
            #pragma unroll
            for (int e = 0; e < 4; e++) acc[mt][nt][e] = 0.f;

    for (int k = k0; k < kEnd; k += 32) {
        int kw = kEnd - k;                    // valid width this iter (uniform per block)
        if (kw >= 32) {
            #pragma unroll
            for (int i = 0; i < 2; i++) {
                int idx = tid + i * 256;      // 0..511 -> 64 rows x 8 float4
                int r = idx >> 3, c4 = idx & 7;
                float4 v = *(const float4*)(A + (size_t)r * lda + k + c4 * 4);
                sA[r][c4*4+0] = v.x; sA[r][c4*4+1] = v.y;
                sA[r][c4*4+2] = v.z; sA[r][c4*4+3] = v.w;
            }
        } else {
            #pragma unroll
            for (int i = 0; i < 2; i++) {
                int idx = tid + i * 256;
                int r = idx >> 3, c4 = idx & 7;
                #pragma unroll
                for (int e = 0; e < 4; e++) {
                    int kk = c4 * 4 + e;
                    sA[r][kk] = (kk < kw) ? A[(size_t)r * lda + k + kk] : 0.f;
                }
            }
        }
        #pragma unroll
        for (int i = 0; i < 8; i++) {
            int idx = tid + i * 256;          // 0..2047 -> 32 k-rows x 64 cols
            int r = idx >> 6, c = idx & 63;
            int jg = n0 + c;
            sW[r][c] = (r < kw && jg < N) ? W[(size_t)(k + r) * N + jg] : 0.f;
        }
        __syncthreads();
        #pragma unroll
        for (int ks = 0; ks < 32; ks += 8) {
            uint32_t ah[2][4], al[2][4], bh[2][2], bl[2][2];
            #pragma unroll
            for (int mt = 0; mt < 2; mt++) {
                int mr = wm * 32 + mt * 16;
                split_tf32(sA[mr + g    ][ks + tg    ], ah[mt][0], al[mt][0]);
                split_tf32(sA[mr + g + 8][ks + tg    ], ah[mt][1], al[mt][1]);
                split_tf32(sA[mr + g    ][ks + tg + 4], ah[mt][2], al[mt][2]);
                split_tf32(sA[mr + g + 8][ks + tg + 4], ah[mt][3], al[mt][3]);
            }
            #pragma unroll
            for (int nt = 0; nt < 2; nt++) {
                int nc = wn * 16 + nt * 8;
                split_tf32(sW[ks + tg    ][nc + g], bh[nt][0], bl[nt][0]);
                split_tf32(sW[ks + tg + 4][nc + g], bh[nt][1], bl[nt][1]);
            }
            // TF32x3: acc += lo*hi + hi*lo + hi*hi (small terms first)
            #pragma unroll
            for (int mt = 0; mt < 2; mt++)
                #pragma unroll
                for (int nt = 0; nt < 2; nt++) {
                    mma_tf32(acc[mt][nt], al[mt], bh[nt]);
                    mma_tf32(acc[mt][nt], ah[mt], bl[nt]);
                    mma_tf32(acc[mt][nt], ah[mt], bh[nt]);
                }
        }
        __syncthreads();
    }

    float* Cp = out + (mode == 1 ? (size_t)blockIdx.y * 64 * N : 0);
    #pragma unroll
    for (int mt = 0; mt < 2; mt++)
        #pragma unroll
        for (int nt = 0; nt < 2; nt++) {
            int row  = wm * 32 + mt * 16 + g;
            int col0 = n0 + wn * 16 + nt * 8 + tg * 2;
            #pragma unroll
            for (int e = 0; e < 2; e++) {
                int col = col0 + e;
                if (col >= N) continue;
                float bb = (bias && mode != 1) ? bias[col] : 0.f;
                float x0 = acc[mt][nt][e]     + bb;
                float x1 = acc[mt][nt][2 + e] + bb;
                if (mode == 2) { x0 = tanhf(x0); x1 = tanhf(x1); }
                Cp[(size_t)row * N + col]       = x0;
                Cp[(size_t)(row + 8) * N + col] = x1;
            }
        }
}

// ---------------- top-3 selection (+ optional rel gathers) ----------------
__global__ void k_topk(const float* __restrict__ score,     // [B,16]
                       const float* __restrict__ lmask,     // [B,128]
                       const float* __restrict__ land,      // [B,128,300]
                       const float* __restrict__ relmask_in,
                       const float* __restrict__ landrel_in,
                       int which) {
    int b = blockIdx.x;
    __shared__ float sv[128];
    __shared__ int sel[3];
    int tid = threadIdx.x;
    if (tid < 128) sv[tid] = score[b * 16 + (tid >> 3)] * lmask[b * 128 + tid];
    __syncthreads();
    int* top = which ? g_top2 : g_top1;
    float* nbout = which ? g_nb2 : g_nb1;
    if (tid < 32) {
        for (int r = 0; r < 3; r++) {
            float bv = -INFINITY; int bi = 128;
            for (int m = tid; m < 128; m += 32) {
                float v = sv[m];
                if (v > bv || (v == bv && m < bi)) { bv = v; bi = m; }
            }
            #pragma unroll
            for (int off = 16; off; off >>= 1) {
                float ov = __shfl_down_sync(0xffffffffu, bv, off);
                int   oi = __shfl_down_sync(0xffffffffu, bi, off);
                if (ov > bv || (ov == bv && oi < bi)) { bv = ov; bi = oi; }
            }
            if (tid == 0) { sel[r] = bi; top[b * 3 + r] = bi; sv[bi] = -INFINITY; }
            __syncwarp();
        }
    }
    __syncthreads();
    int w = tid >> 5, lane = tid & 31;
    if (w < 3) {
        int m = sel[w];
        const float* p = land + ((size_t)b * 128 + m) * D_;
        float s = 0.f;
        for (int d = lane; d < D_; d += 32) { float v = p[d]; s += v * v; }
        s = wred(s);
        if (lane == 0) nbout[b * 3 + w] = sqrtf(s);
    }
    if (relmask_in && tid < 3)
        g_relmask[b * 3 + tid] = relmask_in[b * 128 + sel[tid]];
    if (landrel_in && tid < 18) {
        int t = tid / 6, r2 = tid % 6;
        g_landrel[b * 18 + tid] = landrel_in[((size_t)b * 128 + sel[t]) * 6 + r2];
    }
}

// ---------------- fused object retrieval + dot-with-query ----------------
// which=0: pano -> writes g_pano_sim and g_a[bs] = <[feature|pano_sim], qfeat>
// which=1: cand -> writes out_logit[bs] = <[cand_feat|new_feat], q2> (rel terms inline)
__global__ void __launch_bounds__(256) k_objret(
        const float* __restrict__ obj, int I,
        const float* __restrict__ land,
        const float* __restrict__ extra,      // feature or cand_feat [B,I,FEAT]
        const float* __restrict__ qbase,      // g_qfeat or g_q2
        const float* __restrict__ crel,       // [B,IMG,6] (which=1 only)
        float* __restrict__ aout, int which) {
    int bi = blockIdx.x;
    int b = bi / I;
    __shared__ float sl[3][D_];
    __shared__ float snb[3];
    __shared__ float ssim[OBJ_][3];
    __shared__ int sbest[3];
    __shared__ float sred[8];
    int tid = threadIdx.x;
    const int* top = which ? g_top2 : g_top1;
    const float* nb = which ? g_nb2 : g_nb1;
    for (int idx = tid; idx < 3 * D_; idx += 256) {
        int t = idx / D_, d = idx % D_;
        sl[t][d] = land[((size_t)b * 128 + top[b * 3 + t]) * D_ + d];
    }
    if (tid < 3) snb[tid] = nb[b * 3 + tid];
    __syncthreads();
    const float* ob = obj + (size_t)bi * OBJ_ * D_;
    int w = tid >> 5, lane = tid & 31;
    for (int o = w; o < OBJ_; o += 8) {
        const float* po = ob + o * D_;
        float d0 = 0.f, d1 = 0.f, d2 = 0.f, nr = 0.f;
        for (int d = lane; d < D_; d += 32) {
            float v = po[d];
            d0 += v * sl[0][d]; d1 += v * sl[1][d]; d2 += v * sl[2][d]; nr += v * v;
        }
        #pragma unroll
        for (int off = 16; off; off >>= 1) {
            d0 += __shfl_down_sync(0xffffffffu, d0, off);
            d1 += __shfl_down_sync(0xffffffffu, d1, off);
            d2 += __shfl_down_sync(0xffffffffu, d2, off);
            nr += __shfl_down_sync(0xffffffffu, nr, off);
        }
        if (lane == 0) {
            float na = sqrtf(nr);
            ssim[o][0] = d0 / fmaxf(na * snb[0], EPS_);
            ssim[o][1] = d1 / fmaxf(na * snb[1], EPS_);
            ssim[o][2] = d2 / fmaxf(na * snb[2], EPS_);
        }
    }
    __syncthreads();
    if (tid < 3) {
        float bv = -INFINITY; int bo = 0;
        for (int o = 0; o < OBJ_; o++) { float v = ssim[o][tid]; if (v > bv) { bv = v; bo = o; } }
        sbest[tid] = bo;
    }
    __syncthreads();

    int qStride = which ? 3097 : 3076;
    int tStride = which ? 307  : 300;
    const float* q = qbase + (size_t)b * qStride;
    float accq = 0.f;
    // base feature dot
    const float* f = extra + (size_t)bi * FEAT_;
    for (int d = tid; d < FEAT_; d += 256) accq += f[d] * q[d];
    // gathered-object dot (+ write for pano)
    float* po = which ? nullptr : (g_pano_sim + (size_t)bi * 900);
    for (int idx = tid; idx < 3 * D_; idx += 256) {
        int t = idx / D_, d = idx % D_;
        float v = ob[sbest[t] * D_ + d];
        if (!which) po[t * 300 + d] = v;
        accq += v * q[FEAT_ + t * tStride + d];
    }
    // relation terms (cand only)
    if (which && tid < 21) {
        int t = tid / 7, r = tid % 7;
        const float* cr = crel + (size_t)bi * 6;
        if (r < 6) {
            accq += cr[r] * g_relmask[b * 3 + t] * q[FEAT_ + t * 307 + 300 + r];
        } else {
            float dot = 0.f;
            #pragma unroll
            for (int rr = 0; rr < 6; rr++) dot += cr[rr] * g_landrel[b * 18 + t * 6 + rr];
            accq += dot * q[FEAT_ + t * 307 + 306];
        }
    }
    accq = block_reduce(accq, sred);
    if (tid == 0) aout[bi] = accq;
}

// ---------------- attention-weighted feature (softmax inline) ----------------
__global__ void k_attn_feat(const float* __restrict__ feature) {
    int b = blockIdx.y;
    int d = blockIdx.x * 256 + threadIdx.x;
    __shared__ float sp[PANO_];
    __shared__ float sms[2];
    if (threadIdx.x < PANO_) sp[threadIdx.x] = g_a[b * PANO_ + threadIdx.x];
    __syncthreads();
    if (threadIdx.x == 0) {
        float m = -INFINITY;
        for (int i = 0; i < PANO_; i++) m = fmaxf(m, sp[i]);
        float su = 0.f;
        for (int i = 0; i < PANO_; i++) su += expf(sp[i] - m);
        sms[0] = m; sms[1] = su;
    }
    __syncthreads();
    if (threadIdx.x < PANO_)
        sp[threadIdx.x] = expf(sp[threadIdx.x] - sms[0]) / sms[1];
    __syncthreads();
    if (d >= 3076) return;
    float acc = 0.f;
    if (d < FEAT_) {
        const float* f = feature + (size_t)b * PANO_ * FEAT_ + d;
        #pragma unroll 4
        for (int s = 0; s < PANO_; s++) acc += sp[s] * f[(size_t)s * FEAT_];
    } else {
        const float* f = g_pano_sim + (size_t)b * PANO_ * 900 + (d - FEAT_);
        #pragma unroll 4
        for (int s = 0; s < PANO_; s++) acc += sp[s] * f[(size_t)s * 900];
    }
    g_x[(size_t)b * 3140 + 64 + d] = acc;
}

// ---------------- LSTM (fused split-K reduce + bias) ----------------
__global__ void k_lstm(const float* __restrict__ c0,
                       const float* __restrict__ bias,
                       float* __restrict__ out) {
    int idx = blockIdx.x * 256 + threadIdx.x;
    if (idx >= B_ * H_) return;
    int b = idx >> 9, j = idx & 511;
    float g4[4];
    #pragma unroll
    for (int qg = 0; qg < 4; qg++) {
        int col = qg * 512 + j;
        float v = bias[col] + g_gates[(size_t)b * 2048 + col];
        #pragma unroll
        for (int s = 0; s < 4; s++)
            v += g_part[(size_t)s * 64 * 2048 + (size_t)b * 2048 + col];
        g4[qg] = v;
    }
    float ig = sigmoidf_(g4[0]);
    float fg = sigmoidf_(g4[1]);
    float gg = tanhf(g4[2]);
    float og = sigmoidf_(g4[3]);
    float c1 = fg * c0[idx] + ig * gg;
    float h1 = og * tanhf(c1);
    out[OFF_H1 + idx] = h1;
    out[OFF_C1 + idx] = c1;
}

// ---------------- ctx attention ----------------
__global__ void k_ctx_attn(const float* __restrict__ ctx,
                           const unsigned char* __restrict__ cmask,
                           float* __restrict__ out) {
    int b = blockIdx.x;
    int tid = threadIdx.x; // 512
    __shared__ float sqa[H_], slg[CFG_], sattn[CFG_];
    sqa[tid] = g_qa[b * H_ + tid];
    __syncthreads();
    int w = tid >> 5, lane = tid & 31;
    const float* cb = ctx + (size_t)b * CFG_ * H_;
    {
        float acc = 0.f;
        const float* cw = cb + w * H_;
        for (int d = lane; d < H_; d += 32) acc += cw[d] * sqa[d];
        acc = wred(acc);
        if (lane == 0) slg[w] = cmask[b * CFG_ + w] ? -INFINITY : acc;
    }
    __syncthreads();
    if (tid == 0) {
        float m = -INFINITY;
        for (int s = 0; s < CFG_; s++) m = fmaxf(m, slg[s]);
        float su = 0.f;
        for (int s = 0; s < CFG_; s++) { float e = expf(slg[s] - m); sattn[s] = e; su += e; }
        float inv = 1.f / su;
        for (int s = 0; s < CFG_; s++) { sattn[s] *= inv; out[OFF_CA + b * CFG_ + s] = sattn[s]; }
    }
    __syncthreads();
    float acc = 0.f;
    #pragma unroll
    for (int s = 0; s < CFG_; s++) acc += sattn[s] * cb[(size_t)s * H_ + tid];
    g_cat[b * 1024 + tid] = acc;
    g_cat[b * 1024 + 512 + tid] = out[OFF_H1 + b * H_ + tid];
}

// ---------------- host launcher ----------------
extern "C" void kernel_launch(void* const* d_in, const int* in_sizes, int n_in,
                              void* d_out, int out_size) {
    const float* action    = (const float*)d_in[0];
    const float* feature   = (const float*)d_in[1];
    const float* cand_feat = (const float*)d_in[2];
    const float* prev_h1   = (const float*)d_in[3];
    const float* c_0       = (const float*)d_in[4];
    const float* ctx       = (const float*)d_in[5];
    const float* s_0       = (const float*)d_in[6];
    const float* land      = (const float*)d_in[7];
    const float* cand_obj  = (const float*)d_in[8];
    const float* lmask     = (const float*)d_in[9];
    const float* landrel   = (const float*)d_in[10];
    const float* relmask   = (const float*)d_in[11];
    const float* crel      = (const float*)d_in[12];
    const float* pano_obj  = (const float*)d_in[13];
    const float* embW      = (const float*)d_in[14];
    const float* embB      = (const float*)d_in[15];
    const float* W_ih      = (const float*)d_in[16];
    const float* W_hh      = (const float*)d_in[17];
    const float* b_lstm    = (const float*)d_in[18];
    const float* feat_in_W = (const float*)d_in[19];
    const float* att_in_W  = (const float*)d_in[20];
    const float* att_out_W = (const float*)d_in[21];
    const float* cand_in_W = (const float*)d_in[22];
    const unsigned char* cmask = (const unsigned char*)d_in[23];
    float* out = (float*)d_out;

    float *p_x, *p_qfeat, *p_gates, *p_qa, *p_cat, *p_q2, *p_part, *p_a;
    cudaGetSymbolAddress((void**)&p_x,     g_x);
    cudaGetSymbolAddress((void**)&p_qfeat, g_qfeat);
    cudaGetSymbolAddress((void**)&p_gates, g_gates);
    cudaGetSymbolAddress((void**)&p_qa,    g_qa);
    cudaGetSymbolAddress((void**)&p_cat,   g_cat);
    cudaGetSymbolAddress((void**)&p_q2,    g_q2);
    cudaGetSymbolAddress((void**)&p_part,  g_part);
    cudaGetSymbolAddress((void**)&p_a,     g_a);

    // --- stage 1: prep ---
    k_action_embed<<<32, 128>>>(action, embW, embB);
    k_topk<<<B_, 128>>>(s_0, lmask, land, nullptr, nullptr, 0);
    // qfeat = prev_h1 @ feat_in_W  [64,3076], K=512
    k_gemm_tc<<<dim3(49, 1), 256>>>(prev_h1, 512, feat_in_W, 3076, 512, 512, p_qfeat, nullptr, 0);
    // pano object retrieval + feature-attention logits fused
    k_objret<<<B_ * PANO_, 256>>>(pano_obj, PANO_, land, feature, p_qfeat, nullptr, p_a, 0);
    // attention-weighted feature (softmax inline) -> g_x[:,64:]
    k_attn_feat<<<dim3(13, B_), 256>>>(feature);

    // --- LSTM gates ---
    k_gemm_tc<<<dim3(32, 1), 256>>>(prev_h1, 512, W_hh, 2048, 512, 512, p_gates, nullptr, 0);
    k_gemm_tc<<<dim3(32, 4), 256>>>(p_x, 3140, W_ih, 2048, 3140, 800, p_part, nullptr, 1);
    k_lstm<<<128, 256>>>(c_0, b_lstm, out);

    // --- ctx attention ---
    k_gemm_tc<<<dim3(8, 1), 256>>>(out + OFF_H1, 512, att_in_W, 512, 512, 512, p_qa, nullptr, 0);
    k_ctx_attn<<<B_, 512>>>(ctx, cmask, out);
    // h_tilde = tanh([wctx|h1] @ att_out_W)  -> out directly
    k_gemm_tc<<<dim3(8, 1), 256>>>(p_cat, 1024, att_out_W, 512, 1024, 1024, out + OFF_HT, nullptr, 2);

    // --- candidate retrieval + logit ---
    k_topk<<<B_, 128>>>(out + OFF_CA, lmask, land, relmask, landrel, 1);
    k_gemm_tc<<<dim3(49, 1), 256>>>(out + OFF_HT, 512, cand_in_W, 3097, 512, 512, p_q2, nullptr, 0);
    k_objret<<<B_ * IMG_, 256>>>(cand_obj, IMG_, land, cand_feat, p_q2, crel, out + OFF_LOG, 1);
}